// round 4
// baseline (speedup 1.0000x reference)
#include <cuda_runtime.h>
#include <cuda_bf16.h>

// DeepFilter: 5-tap complex FIR over first 256 freq bins + passthrough of the rest.
// spec:  [B=8][2][T=4096][F=481]  fp32
// coefs: [B=8][10][T=4096][256]   fp32   (10 = {real taps 0..4, imag taps 0..4})
// out:   [B=8][2][T=4096][F=481]  fp32
//
// DRAM-bound (~590 MB compulsory). Mapping: thread = freq bin (perfect lane
// coalescing on spec/coefs/out), block = 4 consecutive time steps sharing one
// 8-row spec window in registers (16 spec LDGs per 4 outputs vs 40 naive).

#define NUM_FREQS 256
#define FRAME_SIZE 5
#define B_DIM 8
#define T_DIM 4096
#define F_TOTAL 481
#define F_TAIL (F_TOTAL - NUM_FREQS)   // 225

__global__ __launch_bounds__(256) void deepfilter_kernel(
    const float* __restrict__ spec,
    const float* __restrict__ coefs,
    float* __restrict__ out)
{
    const int blk = blockIdx.x;              // 0 .. 8191
    const int b   = blk >> 10;               // 1024 blocks per batch (T/4)
    const int t0  = (blk & 1023) << 2;       // 4 time steps per block
    const int f   = threadIdx.x;             // 0 .. 255

    const int spec_b0 = (b * 2) * T_DIM * F_TOTAL;     // real channel base
    const int spec_b1 = spec_b0 + T_DIM * F_TOTAL;     // imag channel base

    // Spec window: ts = t0-4 .. t0+3  (8 rows, shared by the 4 outputs)
    float pr[8], pi[8];
#pragma unroll
    for (int k = 0; k < 8; ++k) {
        const int ts = t0 - 4 + k;
        if (ts >= 0) {
            const int so = ts * F_TOTAL + f;
            pr[k] = spec[spec_b0 + so];
            pi[k] = spec[spec_b1 + so];
        } else {
            pr[k] = 0.0f;
            pi[k] = 0.0f;
        }
    }

    const int c_row  = ((b * 10) * T_DIM + t0) * NUM_FREQS + f;
    const int c_kstr = T_DIM * NUM_FREQS;    // per-tap stride

    float re[4] = {0.f, 0.f, 0.f, 0.f};
    float im[4] = {0.f, 0.f, 0.f, 0.f};

#pragma unroll
    for (int tt = 0; tt < 4; ++tt) {
        const int cb = c_row + tt * NUM_FREQS;
#pragma unroll
        for (int k = 0; k < FRAME_SIZE; ++k) {
            const float cr = __ldcs(&coefs[cb + k * c_kstr]);
            const float ci = __ldcs(&coefs[cb + (k + FRAME_SIZE) * c_kstr]);
            const float sr = pr[tt + k];
            const float si = pi[tt + k];
            re[tt] = fmaf(sr,  cr, re[tt]);
            re[tt] = fmaf(-si, ci, re[tt]);
            im[tt] = fmaf(si,  cr, im[tt]);
            im[tt] = fmaf(sr,  ci, im[tt]);
        }
    }

    const int orow = t0 * F_TOTAL + f;
#pragma unroll
    for (int tt = 0; tt < 4; ++tt) {
        out[spec_b0 + orow + tt * F_TOTAL] = re[tt];
        out[spec_b1 + orow + tt * F_TOTAL] = im[tt];
    }

    // Passthrough bins f = 256..480, both channels, 4 rows:
    // per row 2*225 = 450 elems -> 2 strided iters of 256 threads.
#pragma unroll
    for (int r = 0; r < 4; ++r) {
#pragma unroll
        for (int u = 0; u < 2; ++u) {
            const int idx = threadIdx.x + u * 256;
            if (idx < 2 * F_TAIL) {
                const int ch = (idx >= F_TAIL) ? 1 : 0;
                const int j  = idx - ch * F_TAIL;
                const int o  = (b * 2 + ch) * T_DIM * F_TOTAL
                             + (t0 + r) * F_TOTAL + NUM_FREQS + j;
                out[o] = __ldcs(&spec[o]);
            }
        }
    }
}

extern "C" void kernel_launch(void* const* d_in, const int* in_sizes, int n_in,
                              void* d_out, int out_size)
{
    const float* spec  = (const float*)d_in[0];
    const float* coefs = (const float*)d_in[1];
    float* out = (float*)d_out;

    dim3 grid(B_DIM * T_DIM / 4);
    dim3 block(256);
    deepfilter_kernel<<<grid, block>>>(spec, coefs, out);
}